// round 1
// baseline (speedup 1.0000x reference)
#include <cuda_runtime.h>
#include <cuda_bf16.h>

// Problem constants
constexpr int Bb = 16384;
constexpr int Ss = 3;
constexpr int Dd = 512;
constexpr int Hh = 8;
constexpr int HDd = 64;
constexpr int FFf = 2048;
constexpr int Mm = Bb * Ss;  // 49152 tokens

// Scratch (device globals: allocation-free rule)
__device__ float g_X [Mm * Dd];        // stacked input + pos
__device__ float g_QKV[Mm * 3 * Dd];   // packed qkv
__device__ float g_O [Mm * Dd];        // attention output (pre-proj)
__device__ float g_Y1[Mm * Dd];        // x + attn_out (pre-LN1)
__device__ float g_X1[Mm * Dd];        // LN1 output
__device__ float g_H [Mm * FFf];       // relu(ff1)
__device__ float g_Y2[Mm * Dd];        // x1 + ff2 (pre-LN2)

// ---------------- f32x2 helpers ----------------
__device__ __forceinline__ void fma2(unsigned long long& acc,
                                     unsigned long long a,
                                     unsigned long long b) {
    asm("fma.rn.f32x2 %0, %1, %2, %0;" : "+l"(acc) : "l"(a), "l"(b));
}
__device__ __forceinline__ unsigned long long pack2(float lo, float hi) {
    unsigned long long r;
    asm("mov.b64 %0, {%1, %2};" : "=l"(r) : "f"(lo), "f"(hi));
    return r;
}
__device__ __forceinline__ void unpack2(unsigned long long v, float& lo, float& hi) {
    asm("mov.b64 {%0, %1}, %2;" : "=f"(lo), "=f"(hi) : "l"(v));
}

// ---------------- build X = stack(feat)+pos ----------------
__global__ void build_x_kernel(const float* __restrict__ f0,
                               const float* __restrict__ f1,
                               const float* __restrict__ f2,
                               const float* __restrict__ pos,
                               float* __restrict__ X) {
    int idx = blockIdx.x * blockDim.x + threadIdx.x;   // float4 index
    // total float4s = Mm*Dd/4 = 6291456
    int m  = idx >> 7;          // row (Dd/4 = 128 float4 per row)
    int c4 = idx & 127;         // float4 col
    int b  = m / 3;
    int s  = m - b * 3;
    const float* f = (s == 0) ? f0 : ((s == 1) ? f1 : f2);
    const float4 a = *reinterpret_cast<const float4*>(&f[b * Dd + c4 * 4]);
    const float4 p = *reinterpret_cast<const float4*>(&pos[s * Dd + c4 * 4]);
    float4 o;
    o.x = a.x + p.x; o.y = a.y + p.y; o.z = a.z + p.z; o.w = a.w + p.w;
    *reinterpret_cast<float4*>(&X[m * Dd + c4 * 4]) = o;
}

// ---------------- SGEMM: C[M,N] = A[M,K] * W[N,K]^T + bias (+R) (relu?) ----------------
// Tiles: BM=128, BN=128, BK=16; 256 threads; 8x8 per thread; f32x2 FMAs; double-buffered.
template <int N, int K, bool RELU, bool RESID>
__global__ __launch_bounds__(256, 2)
void sgemm_nt(const float* __restrict__ A, const float* __restrict__ W,
              const float* __restrict__ bias, const float* __restrict__ R,
              float* __restrict__ C) {
    constexpr int BM = 128, BN = 128, BK = 16;
    constexpr int KT = K / BK;

    __shared__ float As[2][BK][BM];
    __shared__ float Bs[2][BK][BN];

    const int tid = threadIdx.x;
    const int m0 = blockIdx.y * BM;
    const int n0 = blockIdx.x * BN;

    // compute mapping: 8 warps as 4x2, lanes as 4x8 -> 8x8 per thread
    const int warp = tid >> 5, lane = tid & 31;
    const int wm = warp >> 1, wn = warp & 1;
    const int lm = lane >> 3, ln = lane & 7;
    const int arow = wm * 32 + lm * 8;   // m offset in tile
    const int bcol = wn * 64 + ln * 8;   // n offset in tile

    // load mapping: 512 float4 per tile; thread loads ids {tid, tid+256}
    const int lrow = tid >> 2;           // 0..63 (second = +64)
    const int lk4  = (tid & 3) * 4;      // k sub-offset (0,4,8,12)

    const float* Ard = A + (size_t)(m0 + lrow) * K + lk4;
    const float* Wrd = W + (size_t)(n0 + lrow) * K + lk4;

    unsigned long long acc[8][4];
#pragma unroll
    for (int i = 0; i < 8; i++)
#pragma unroll
        for (int j = 0; j < 4; j++) acc[i][j] = 0ull;   // (+0.f,+0.f)

    // prefetch tile 0 -> smem buf 0
    {
        float4 a0 = *reinterpret_cast<const float4*>(Ard);
        float4 a1 = *reinterpret_cast<const float4*>(Ard + (size_t)64 * K);
        float4 b0 = *reinterpret_cast<const float4*>(Wrd);
        float4 b1 = *reinterpret_cast<const float4*>(Wrd + (size_t)64 * K);
        As[0][lk4 + 0][lrow] = a0.x; As[0][lk4 + 1][lrow] = a0.y;
        As[0][lk4 + 2][lrow] = a0.z; As[0][lk4 + 3][lrow] = a0.w;
        As[0][lk4 + 0][lrow + 64] = a1.x; As[0][lk4 + 1][lrow + 64] = a1.y;
        As[0][lk4 + 2][lrow + 64] = a1.z; As[0][lk4 + 3][lrow + 64] = a1.w;
        Bs[0][lk4 + 0][lrow] = b0.x; Bs[0][lk4 + 1][lrow] = b0.y;
        Bs[0][lk4 + 2][lrow] = b0.z; Bs[0][lk4 + 3][lrow] = b0.w;
        Bs[0][lk4 + 0][lrow + 64] = b1.x; Bs[0][lk4 + 1][lrow + 64] = b1.y;
        Bs[0][lk4 + 2][lrow + 64] = b1.z; Bs[0][lk4 + 3][lrow + 64] = b1.w;
    }
    __syncthreads();

    int buf = 0;
#pragma unroll 1
    for (int kk = 0; kk < KT; kk++) {
        float4 pa0, pa1, pb0, pb1;
        if (kk + 1 < KT) {
            const float* Ap = Ard + (size_t)(kk + 1) * BK;
            const float* Wp = Wrd + (size_t)(kk + 1) * BK;
            pa0 = *reinterpret_cast<const float4*>(Ap);
            pa1 = *reinterpret_cast<const float4*>(Ap + (size_t)64 * K);
            pb0 = *reinterpret_cast<const float4*>(Wp);
            pb1 = *reinterpret_cast<const float4*>(Wp + (size_t)64 * K);
        }

#pragma unroll
        for (int k = 0; k < BK; k++) {
            unsigned long long av[8], bv[4];
#pragma unroll
            for (int i = 0; i < 8; i++) {
                float a = As[buf][k][arow + i];
                av[i] = pack2(a, a);
            }
#pragma unroll
            for (int j = 0; j < 4; j++) {
                bv[j] = *reinterpret_cast<const unsigned long long*>(
                    &Bs[buf][k][bcol + 2 * j]);
            }
#pragma unroll
            for (int i = 0; i < 8; i++)
#pragma unroll
                for (int j = 0; j < 4; j++) fma2(acc[i][j], av[i], bv[j]);
        }

        if (kk + 1 < KT) {
            int nb = buf ^ 1;
            As[nb][lk4 + 0][lrow] = pa0.x; As[nb][lk4 + 1][lrow] = pa0.y;
            As[nb][lk4 + 2][lrow] = pa0.z; As[nb][lk4 + 3][lrow] = pa0.w;
            As[nb][lk4 + 0][lrow + 64] = pa1.x; As[nb][lk4 + 1][lrow + 64] = pa1.y;
            As[nb][lk4 + 2][lrow + 64] = pa1.z; As[nb][lk4 + 3][lrow + 64] = pa1.w;
            Bs[nb][lk4 + 0][lrow] = pb0.x; Bs[nb][lk4 + 1][lrow] = pb0.y;
            Bs[nb][lk4 + 2][lrow] = pb0.z; Bs[nb][lk4 + 3][lrow] = pb0.w;
            Bs[nb][lk4 + 0][lrow + 64] = pb1.x; Bs[nb][lk4 + 1][lrow + 64] = pb1.y;
            Bs[nb][lk4 + 2][lrow + 64] = pb1.z; Bs[nb][lk4 + 3][lrow + 64] = pb1.w;
            __syncthreads();
        }
        buf ^= 1;
    }

    // epilogue
#pragma unroll
    for (int i = 0; i < 8; i++) {
        const int row = m0 + arow + i;
#pragma unroll
        for (int j = 0; j < 4; j++) {
            const int col = n0 + bcol + 2 * j;
            float lo, hi;
            unpack2(acc[i][j], lo, hi);
            const float2 bb = *reinterpret_cast<const float2*>(&bias[col]);
            lo += bb.x; hi += bb.y;
            if (RESID) {
                const float2 rr = *reinterpret_cast<const float2*>(
                    &R[(size_t)row * N + col]);
                lo += rr.x; hi += rr.y;
            }
            if (RELU) { lo = fmaxf(lo, 0.f); hi = fmaxf(hi, 0.f); }
            float2 o; o.x = lo; o.y = hi;
            *reinterpret_cast<float2*>(&C[(size_t)row * N + col]) = o;
        }
    }
}

// ---------------- attention: one warp per (b,h) ----------------
__global__ void attn_kernel(const float* __restrict__ QKV, float* __restrict__ O) {
    const int warp = threadIdx.x >> 5;
    const int lane = threadIdx.x & 31;
    const int idx = blockIdx.x * 4 + warp;   // < Bb*Hh
    const int b = idx >> 3;
    const int h = idx & 7;

    float q[3][2], k[3][2], v[3][2];
#pragma unroll
    for (int s = 0; s < 3; s++) {
        const float* p = QKV + (size_t)(b * 3 + s) * (3 * Dd) + h * HDd;
        q[s][0] = p[lane];          q[s][1] = p[lane + 32];
        k[s][0] = p[Dd + lane];     k[s][1] = p[Dd + lane + 32];
        v[s][0] = p[2 * Dd + lane]; v[s][1] = p[2 * Dd + lane + 32];
    }

    float sc[3][3];
#pragma unroll
    for (int i = 0; i < 3; i++)
#pragma unroll
        for (int j = 0; j < 3; j++) {
            float p = q[i][0] * k[j][0] + q[i][1] * k[j][1];
#pragma unroll
            for (int off = 16; off > 0; off >>= 1)
                p += __shfl_xor_sync(0xFFFFFFFFu, p, off);
            sc[i][j] = p * 0.125f;   // 1/sqrt(64)
        }

#pragma unroll
    for (int i = 0; i < 3; i++) {
        const float mx = fmaxf(fmaxf(sc[i][0], sc[i][1]), sc[i][2]);
        const float e0 = expf(sc[i][0] - mx);
        const float e1 = expf(sc[i][1] - mx);
        const float e2 = expf(sc[i][2] - mx);
        const float inv = 1.f / (e0 + e1 + e2);
        const float a0 = e0 * inv, a1 = e1 * inv, a2 = e2 * inv;
        const float o0 = a0 * v[0][0] + a1 * v[1][0] + a2 * v[2][0];
        const float o1 = a0 * v[0][1] + a1 * v[1][1] + a2 * v[2][1];
        float* op = O + (size_t)(b * 3 + i) * Dd + h * HDd;
        op[lane] = o0;
        op[lane + 32] = o1;
    }
}

// ---------------- layernorm over D=512, one block(128) per row ----------------
__device__ __forceinline__ void block_stats(float s, float sq, int t,
                                            float* shs, float* shq,
                                            float& mu, float& rs) {
#pragma unroll
    for (int o = 16; o > 0; o >>= 1) {
        s  += __shfl_xor_sync(0xFFFFFFFFu, s, o);
        sq += __shfl_xor_sync(0xFFFFFFFFu, sq, o);
    }
    const int w = t >> 5;
    if ((t & 31) == 0) { shs[w] = s; shq[w] = sq; }
    __syncthreads();
    const float ts = shs[0] + shs[1] + shs[2] + shs[3];
    const float tq = shq[0] + shq[1] + shq[2] + shq[3];
    mu = ts * (1.f / 512.f);
    const float var = tq * (1.f / 512.f) - mu * mu;
    rs = rsqrtf(var + 1e-5f);
}

__global__ void ln_kernel(const float* __restrict__ Y,
                          const float* __restrict__ g,
                          const float* __restrict__ bta,
                          float* __restrict__ X) {
    const int row = blockIdx.x;
    const int t = threadIdx.x;   // 128
    __shared__ float shs[4], shq[4];
    const float4 v = *reinterpret_cast<const float4*>(&Y[(size_t)row * Dd + t * 4]);
    float mu, rs;
    block_stats(v.x + v.y + v.z + v.w,
                v.x * v.x + v.y * v.y + v.z * v.z + v.w * v.w,
                t, shs, shq, mu, rs);
    const float4 gg = *reinterpret_cast<const float4*>(&g[t * 4]);
    const float4 bb = *reinterpret_cast<const float4*>(&bta[t * 4]);
    float4 o;
    o.x = (v.x - mu) * rs * gg.x + bb.x;
    o.y = (v.y - mu) * rs * gg.y + bb.y;
    o.z = (v.z - mu) * rs * gg.z + bb.z;
    o.w = (v.w - mu) * rs * gg.w + bb.w;
    *reinterpret_cast<float4*>(&X[(size_t)row * Dd + t * 4]) = o;
}

// ---------------- LN2 + mean over S -> out[B,D], one block(128) per batch ----------------
__global__ void ln_mean_kernel(const float* __restrict__ Y,
                               const float* __restrict__ g,
                               const float* __restrict__ bta,
                               float* __restrict__ out) {
    const int b = blockIdx.x;
    const int t = threadIdx.x;
    __shared__ float shs[4], shq[4];
    const float4 gg = *reinterpret_cast<const float4*>(&g[t * 4]);
    const float4 bb = *reinterpret_cast<const float4*>(&bta[t * 4]);
    float4 accv = make_float4(0.f, 0.f, 0.f, 0.f);
#pragma unroll
    for (int s = 0; s < 3; s++) {
        const int row = b * 3 + s;
        const float4 v = *reinterpret_cast<const float4*>(&Y[(size_t)row * Dd + t * 4]);
        float mu, rs;
        block_stats(v.x + v.y + v.z + v.w,
                    v.x * v.x + v.y * v.y + v.z * v.z + v.w * v.w,
                    t, shs, shq, mu, rs);
        accv.x += (v.x - mu) * rs * gg.x + bb.x;
        accv.y += (v.y - mu) * rs * gg.y + bb.y;
        accv.z += (v.z - mu) * rs * gg.z + bb.z;
        accv.w += (v.w - mu) * rs * gg.w + bb.w;
        __syncthreads();   // protect shared stats for next s
    }
    const float inv3 = 1.f / 3.f;
    float4 o;
    o.x = accv.x * inv3; o.y = accv.y * inv3; o.z = accv.z * inv3; o.w = accv.w * inv3;
    *reinterpret_cast<float4*>(&out[(size_t)b * Dd + t * 4]) = o;
}

// ---------------- launch ----------------
extern "C" void kernel_launch(void* const* d_in, const int* in_sizes, int n_in,
                              void* d_out, int out_size) {
    const float* feat0 = (const float*)d_in[0];
    const float* feat1 = (const float*)d_in[1];
    const float* feat2 = (const float*)d_in[2];
    const float* pos   = (const float*)d_in[3];
    const float* w_in  = (const float*)d_in[4];
    const float* b_in  = (const float*)d_in[5];
    const float* w_out = (const float*)d_in[6];
    const float* b_out = (const float*)d_in[7];
    const float* ln1g  = (const float*)d_in[8];
    const float* ln1b  = (const float*)d_in[9];
    const float* w1    = (const float*)d_in[10];
    const float* b1    = (const float*)d_in[11];
    const float* w2    = (const float*)d_in[12];
    const float* b2    = (const float*)d_in[13];
    const float* ln2g  = (const float*)d_in[14];
    const float* ln2b  = (const float*)d_in[15];
    float* out = (float*)d_out;

    float *X, *QKV, *O, *Y1, *X1, *Hb, *Y2;
    cudaGetSymbolAddress((void**)&X,  g_X);
    cudaGetSymbolAddress((void**)&QKV, g_QKV);
    cudaGetSymbolAddress((void**)&O,  g_O);
    cudaGetSymbolAddress((void**)&Y1, g_Y1);
    cudaGetSymbolAddress((void**)&X1, g_X1);
    cudaGetSymbolAddress((void**)&Hb, g_H);
    cudaGetSymbolAddress((void**)&Y2, g_Y2);

    // 1. X = stack(feat0..2) + pos
    build_x_kernel<<<(Mm * Dd / 4) / 256, 256>>>(feat0, feat1, feat2, pos, X);

    // 2. QKV = X @ w_in^T + b_in            [M,1536]
    sgemm_nt<1536, 512, false, false><<<dim3(1536 / 128, Mm / 128), 256>>>(
        X, w_in, b_in, nullptr, QKV);

    // 3. attention -> O                     [M,512]
    attn_kernel<<<Bb * Hh / 4, 128>>>(QKV, O);

    // 4. Y1 = O @ w_out^T + b_out + X       [M,512]
    sgemm_nt<512, 512, false, true><<<dim3(512 / 128, Mm / 128), 256>>>(
        O, w_out, b_out, X, Y1);

    // 5. X1 = LN(Y1)
    ln_kernel<<<Mm, 128>>>(Y1, ln1g, ln1b, X1);

    // 6. H = relu(X1 @ w1^T + b1)           [M,2048]
    sgemm_nt<2048, 512, true, false><<<dim3(2048 / 128, Mm / 128), 256>>>(
        X1, w1, b1, nullptr, Hb);

    // 7. Y2 = H @ w2^T + b2 + X1            [M,512]
    sgemm_nt<512, 2048, false, true><<<dim3(512 / 128, Mm / 128), 256>>>(
        Hb, w2, b2, X1, Y2);

    // 8. out = mean_s LN(Y2)
    ln_mean_kernel<<<Bb, 128>>>(Y2, ln2g, ln2b, out);
}